// round 6
// baseline (speedup 1.0000x reference)
#include <cuda_runtime.h>

// Problem constants: b=2, s=4096, h=16, p=n=64, BLOCK_LEN=64
#define NB   2
#define NH   16
#define NC   64
#define PADS 64   // straight tiles: no padding needed (broadcast/contiguous only)
#define PADT 68   // transposed tiles: padded for scalar-transpose stores + bcast reads

typedef unsigned long long ull;

__device__ __forceinline__ ull ffma2(ull a, ull b, ull c) {
    ull d;
    asm("fma.rn.f32x2 %0, %1, %2, %3;" : "=l"(d) : "l"(a), "l"(b), "l"(c));
    return d;
}
__device__ __forceinline__ ull mul2(ull a, ull b) {
    ull d; asm("mul.rn.f32x2 %0, %1, %2;" : "=l"(d) : "l"(a), "l"(b)); return d;
}
__device__ __forceinline__ ull pack2(float x, float y) {
    ull d; asm("mov.b64 %0, {%1, %2};" : "=l"(d) : "f"(x), "f"(y)); return d;
}
__device__ __forceinline__ float2 unpk(ull v) {
    float2 r; asm("mov.b64 {%0, %1}, %2;" : "=f"(r.x), "=f"(r.y) : "l"(v)); return r;
}

// Scratch (__device__ globals; allocation-free rule)
__device__ float g_states[NB*NH*NC*4096];  // chunk states [n][p]; scanned in place
__device__ float g_G[NB*NH*NC*4096];       // masked decay-weighted Gt [s][l]
__device__ float g_tot[NB*NH*NC];          // per-chunk A totals

// ---------------------------------------------------------------------------
// Pass 1: per (b,h,c): cumsum(A);
//   GEMM1: Gt[s][l] = (l>=s) ? em[s] * sum_n B^T[n][s]*(C^T[n][l]*ecl[l]) : 0
//          -> g_G  (em=exp(A[s]-cs[s]), ecl=exp(cs[l]) folded here)
//   GEMM3: St[n][p] = sum_l B[l][n]*w[l]*X[l][p], w=exp(tot-cs)  -> g_states
// 128 threads, 8x4 micro-tiles. B rows for GEMM3 streamed from global (bcast).
// ---------------------------------------------------------------------------
__global__ void __launch_bounds__(128, 4) pass1_kernel(
    const float* __restrict__ X, const float* __restrict__ A,
    const float* __restrict__ B, const float* __restrict__ C)
{
    extern __shared__ float sm[];
    float* Xs  = sm;                          // [64][PADS] X straight
    float* Bt  = sm + 64*PADS;                // [64][PADT] B^T [n][s]
    float* Cte = sm + 64*PADS + 64*PADT;      // [64][PADT] C^T * ecl [n][l]
    __shared__ float s_cs[64], s_w[64], s_em[64], s_ecl[64];

    const int c = blockIdx.x, h = blockIdx.y, b = blockIdx.z;
    const int bhc = (b*NH + h)*NC + c;
    const int tid = threadIdx.x;
    const int tx = tid & 15, ty = tid >> 4;
    const size_t base = ((size_t)((b*4096 + c*64)*NH + h))*64;
    const int col4 = tx*4;

    float av = 0.f;
    if (tid < 64) av = A[(size_t)(b*4096 + c*64 + tid)*NH + h];

    // LDG X,B,C; STS X straight + Bt transposed now; hold C in regs for Cte
    float4 cv[8];
    #pragma unroll
    for (int i = 0; i < 8; i++) {
        const int row = i*8 + ty;
        const size_t g = base + (size_t)row*1024 + col4;
        *(float4*)(Xs + row*PADS + col4) = *(const float4*)(X + g);
        float4 bf = *(const float4*)(B + g);
        cv[i] = *(const float4*)(C + g);
        const float* bp = (const float*)&bf;
        #pragma unroll
        for (int q = 0; q < 4; q++) {
            const int eq = (q + (tx >> 1)) & 3;     // rotation: <=2-way
            Bt[(col4 + eq)*PADT + row] = bp[eq];
        }
    }

    // inclusive cumsum of A (threads 0..63)
    if (tid < 64) {
        float v = av;
        #pragma unroll
        for (int o = 1; o < 32; o <<= 1) {
            float t = __shfl_up_sync(0xffffffffu, v, o);
            if ((tid & 31) >= o) v += t;
        }
        s_cs[tid] = v;
    }
    __syncthreads();
    if (tid >= 32 && tid < 64) s_cs[tid] += s_cs[31];
    __syncthreads();
    if (tid < 64) {
        const float csl = s_cs[tid], total = s_cs[63];
        s_ecl[tid] = __expf(csl);
        s_em[tid]  = __expf(av - csl);
        s_w[tid]   = __expf(total - csl);
        if (tid == 63) g_tot[bhc] = total;
    }
    __syncthreads();

    // STS Cte (C^T scaled by ecl[row])
    #pragma unroll
    for (int i = 0; i < 8; i++) {
        const int row = i*8 + ty;
        const float e = s_ecl[row];
        float cf[4] = {cv[i].x*e, cv[i].y*e, cv[i].z*e, cv[i].w*e};
        #pragma unroll
        for (int q = 0; q < 4; q++) {
            const int eq = (q + (tx >> 1)) & 3;
            Cte[(col4 + eq)*PADT + row] = cf[eq];
        }
    }
    __syncthreads();

    const int rb = ty*8, cb = col4;

    // ---- GEMM1: Gt[s][l], rows s=rb(8), cols l=cb(4), k=n ----
    {
        ull acc[8][2] = {};
        #pragma unroll 4
        for (int k = 0; k < 64; k++) {
            float af[8];
            *(float4*)(af)     = *(const float4*)(Bt + k*PADT + rb);
            *(float4*)(af + 4) = *(const float4*)(Bt + k*PADT + rb + 4);
            float4 bf = *(const float4*)(Cte + k*PADT + cb);
            const ull* bp = (const ull*)&bf;
            #pragma unroll
            for (int i = 0; i < 8; i++) {
                const ull ad = pack2(af[i], af[i]);
                acc[i][0] = ffma2(ad, bp[0], acc[i][0]);
                acc[i][1] = ffma2(ad, bp[1], acc[i][1]);
            }
        }
        float* gt = g_G + (size_t)bhc*4096;
        #pragma unroll
        for (int i = 0; i < 8; i++) {
            const int s = rb + i;
            const float em = s_em[s];
            float2 p0 = unpk(acc[i][0]), p1 = unpk(acc[i][1]);
            float4 v;
            v.x = (cb + 0 >= s) ? p0.x * em : 0.f;
            v.y = (cb + 1 >= s) ? p0.y * em : 0.f;
            v.z = (cb + 2 >= s) ? p1.x * em : 0.f;
            v.w = (cb + 3 >= s) ? p1.y * em : 0.f;
            *(float4*)(gt + s*64 + cb) = v;
        }
    }

    // ---- GEMM3: St[n][p], rows n=rb, cols p=cb, k=l.
    //      a-frag = B[k][rb..rb+8] streamed from global (bcast, L1/L2-hot),
    //      w folded into b-frag (2x mul.f32x2). ----
    {
        ull acc[8][2] = {};
        const float* Bb = B + base;
        float4 ga = __ldg((const float4*)(Bb + rb));
        float4 gb = __ldg((const float4*)(Bb + rb + 4));
        #pragma unroll 4
        for (int k = 0; k < 64; k++) {
            float4 na, nb;
            if (k < 63) {
                na = __ldg((const float4*)(Bb + (size_t)(k+1)*1024 + rb));
                nb = __ldg((const float4*)(Bb + (size_t)(k+1)*1024 + rb + 4));
            }
            float4 xf = *(const float4*)(Xs + k*PADS + cb);
            const ull* xp = (const ull*)&xf;
            const float wl = s_w[k];
            const ull wp = pack2(wl, wl);
            const ull xw0 = mul2(xp[0], wp);
            const ull xw1 = mul2(xp[1], wp);
            const float* ap = (const float*)&ga;
            const float* aq = (const float*)&gb;
            #pragma unroll
            for (int i = 0; i < 4; i++) {
                const ull ad = pack2(ap[i], ap[i]);
                acc[i][0] = ffma2(ad, xw0, acc[i][0]);
                acc[i][1] = ffma2(ad, xw1, acc[i][1]);
            }
            #pragma unroll
            for (int i = 0; i < 4; i++) {
                const ull ad = pack2(aq[i], aq[i]);
                acc[4+i][0] = ffma2(ad, xw0, acc[4+i][0]);
                acc[4+i][1] = ffma2(ad, xw1, acc[4+i][1]);
            }
            ga = na; gb = nb;
        }
        float* st = g_states + (size_t)bhc*4096;
        #pragma unroll
        for (int i = 0; i < 8; i++) {
            float2 p0 = unpk(acc[i][0]), p1 = unpk(acc[i][1]);
            *(float4*)(st + (rb+i)*64 + cb) = make_float4(p0.x, p0.y, p1.x, p1.y);
        }
    }
}

// ---------------------------------------------------------------------------
// Pass 2: inter-chunk scan, in place. S_out[c] = S_before; S = e_c*(S + v_c).
// ---------------------------------------------------------------------------
__global__ void __launch_bounds__(128) pass2_kernel()
{
    __shared__ float se[NC];
    const int slice = blockIdx.x, bh = blockIdx.y;
    const int tid = threadIdx.x;

    if (tid < NC) se[tid] = __expf(g_tot[bh*NC + tid]);
    __syncthreads();

    float* p = g_states + (size_t)bh*NC*4096 + slice*512 + tid*4;
    float4 v[8];
    #pragma unroll
    for (int j = 0; j < 8; j++) v[j] = *(float4*)(p + (size_t)j*4096);

    float4 S = make_float4(0.f, 0.f, 0.f, 0.f);
    #pragma unroll 8
    for (int c = 0; c < NC; c++) {
        float4 cur = v[c & 7];
        *(float4*)(p + (size_t)c*4096) = S;           // state BEFORE chunk c
        const float e = se[c];
        S.x = e * (S.x + cur.x);
        S.y = e * (S.y + cur.y);
        S.z = e * (S.z + cur.z);
        S.w = e * (S.w + cur.w);
        if (c + 8 < NC) v[c & 7] = *(float4*)(p + (size_t)(c+8)*4096);
    }
}

// ---------------------------------------------------------------------------
// Pass 3: single fused k-loop:
//   Y[l][p] = sum_k Gt[k][l]*X[k][p] + sum_k Cte[k][l]*St[k][p]
// Gt rows streamed from global (bcast, L2-hot) with reg double-buffer.
// 128 threads, 8x4 micro-tiles, 4 CTAs/SM.
// ---------------------------------------------------------------------------
__global__ void __launch_bounds__(128, 4) pass3_kernel(
    const float* __restrict__ X, const float* __restrict__ A,
    const float* __restrict__ C, float* __restrict__ Y)
{
    extern __shared__ float sm[];
    float* Xs  = sm;                          // [64][PADS]
    float* Ss  = sm + 64*PADS;                // [64][PADS]
    float* Cte = sm + 2*64*PADS;              // [64][PADT] C^T * ecl
    __shared__ float s_cs[64], s_ecl[64];

    const int c = blockIdx.x, h = blockIdx.y, b = blockIdx.z;
    const int bhc = (b*NH + h)*NC + c;
    const int tid = threadIdx.x;
    const int tx = tid & 15, ty = tid >> 4;
    const size_t base = ((size_t)((b*4096 + c*64)*NH + h))*64;
    const float* Sg = g_states + (size_t)bhc*4096;
    const int col4 = tx*4;

    float av = 0.f;
    if (tid < 64) av = A[(size_t)(b*4096 + c*64 + tid)*NH + h];

    // LDG X, S straight; hold C in regs
    float4 cv[8];
    #pragma unroll
    for (int i = 0; i < 8; i++) {
        const int row = i*8 + ty;
        *(float4*)(Xs + row*PADS + col4) =
            *(const float4*)(X + base + (size_t)row*1024 + col4);
        *(float4*)(Ss + row*PADS + col4) = *(const float4*)(Sg + row*64 + col4);
        cv[i] = *(const float4*)(C + base + (size_t)row*1024 + col4);
    }

    // cumsum -> ecl only
    if (tid < 64) {
        float v = av;
        #pragma unroll
        for (int o = 1; o < 32; o <<= 1) {
            float t = __shfl_up_sync(0xffffffffu, v, o);
            if ((tid & 31) >= o) v += t;
        }
        s_cs[tid] = v;
    }
    __syncthreads();
    if (tid >= 32 && tid < 64) s_cs[tid] += s_cs[31];
    __syncthreads();
    if (tid < 64) s_ecl[tid] = __expf(s_cs[tid]);
    __syncthreads();

    // STS Cte (C^T scaled by ecl)
    #pragma unroll
    for (int i = 0; i < 8; i++) {
        const int row = i*8 + ty;
        const float e = s_ecl[row];
        float cf[4] = {cv[i].x*e, cv[i].y*e, cv[i].z*e, cv[i].w*e};
        #pragma unroll
        for (int q = 0; q < 4; q++) {
            const int eq = (q + (tx >> 1)) & 3;
            Cte[(col4 + eq)*PADT + row] = cf[eq];
        }
    }
    __syncthreads();

    const int rb = ty*8, cb = col4;

    // fused GEMM2+GEMM4, Gt streamed from global with reg double-buffer
    ull yac[8][2] = {};
    const float* gt = g_G + (size_t)bhc*4096;
    float4 ga = __ldg((const float4*)(gt + rb));
    float4 gb = __ldg((const float4*)(gt + rb + 4));
    #pragma unroll 4
    for (int k = 0; k < 64; k++) {
        float4 na, nb;
        if (k < 63) {
            na = __ldg((const float4*)(gt + (k+1)*64 + rb));
            nb = __ldg((const float4*)(gt + (k+1)*64 + rb + 4));
        }
        float cf[8];
        *(float4*)(cf)     = *(const float4*)(Cte + k*PADT + rb);
        *(float4*)(cf + 4) = *(const float4*)(Cte + k*PADT + rb + 4);
        float4 xf = *(const float4*)(Xs + k*PADS + cb);
        float4 sf = *(const float4*)(Ss + k*PADS + cb);
        const ull* xp = (const ull*)&xf;
        const ull* sp = (const ull*)&sf;
        const float* ap = (const float*)&ga;
        const float* aq = (const float*)&gb;
        #pragma unroll
        for (int i = 0; i < 4; i++) {
            const ull gd = pack2(ap[i], ap[i]);
            yac[i][0] = ffma2(gd, xp[0], yac[i][0]);
            yac[i][1] = ffma2(gd, xp[1], yac[i][1]);
        }
        #pragma unroll
        for (int i = 0; i < 4; i++) {
            const ull gd = pack2(aq[i], aq[i]);
            yac[4+i][0] = ffma2(gd, xp[0], yac[4+i][0]);
            yac[4+i][1] = ffma2(gd, xp[1], yac[4+i][1]);
        }
        #pragma unroll
        for (int i = 0; i < 8; i++) {
            const ull cd = pack2(cf[i], cf[i]);
            yac[i][0] = ffma2(cd, sp[0], yac[i][0]);
            yac[i][1] = ffma2(cd, sp[1], yac[i][1]);
        }
        ga = na; gb = nb;
    }

    #pragma unroll
    for (int i = 0; i < 8; i++) {
        float2 p0 = unpk(yac[i][0]), p1 = unpk(yac[i][1]);
        *(float4*)(Y + base + (size_t)(rb+i)*1024 + cb) =
            make_float4(p0.x, p0.y, p1.x, p1.y);
    }
}

// ---------------------------------------------------------------------------
extern "C" void kernel_launch(void* const* d_in, const int* in_sizes, int n_in,
                              void* d_out, int out_size)
{
    const float* X = (const float*)d_in[0];
    const float* A = (const float*)d_in[1];
    const float* B = (const float*)d_in[2];
    const float* C = (const float*)d_in[3];
    float* Y = (float*)d_out;

    const int smem1 = (64*PADS + 2*64*PADT) * sizeof(float);   // 51,200 B
    const int smem3 = (2*64*PADS + 64*PADT) * sizeof(float);   // 50,176 B
    cudaFuncSetAttribute(pass1_kernel,
                         cudaFuncAttributeMaxDynamicSharedMemorySize, smem1);
    cudaFuncSetAttribute(pass3_kernel,
                         cudaFuncAttributeMaxDynamicSharedMemorySize, smem3);

    dim3 grid(NC, NH, NB);
    pass1_kernel<<<grid, 128, smem1>>>(X, A, B, C);
    pass2_kernel<<<dim3(8, NB*NH), 128>>>();
    pass3_kernel<<<grid, 128, smem3>>>(X, A, C, Y);
}

// round 7
// speedup vs baseline: 1.0644x; 1.0644x over previous
#include <cuda_runtime.h>

// Problem constants: b=2, s=4096, h=16, p=n=64, BLOCK_LEN=64
#define NB   2
#define NH   16
#define NC   64
#define PADS 64   // straight tiles (row-broadcast a / contiguous b reads only)
#define PADT 68   // transposed tiles (mult of 4 for LDS.128; rotated stores <=2-way)

typedef unsigned long long ull;

__device__ __forceinline__ ull ffma2(ull a, ull b, ull c) {
    ull d;
    asm("fma.rn.f32x2 %0, %1, %2, %3;" : "=l"(d) : "l"(a), "l"(b), "l"(c));
    return d;
}
__device__ __forceinline__ ull pack2(float x, float y) {
    ull d; asm("mov.b64 %0, {%1, %2};" : "=l"(d) : "f"(x), "f"(y)); return d;
}
__device__ __forceinline__ float2 unpk(ull v) {
    float2 r; asm("mov.b64 {%0, %1}, %2;" : "=f"(r.x), "=f"(r.y) : "l"(v)); return r;
}

union F4U { float4 f; ull u[2]; };

// Scratch (__device__ globals; allocation-free rule)
__device__ float g_states[NB*NH*NC*4096];  // chunk states [n][p]; scanned in place
__device__ float g_G[NB*NH*NC*4096];       // masked decay-weighted Gt [s][l]
__device__ float g_tot[NB*NH*NC];          // per-chunk A totals

// ---------------------------------------------------------------------------
// Pass 1: per (b,h,c) tile, 128 threads, 8x4 micro-tiles (transposed acc).
//   GEMM1: Gt[s][l] = (l>=s) ? em[s] * sum_n Bt[n][s]*Cte[n][l] : 0   -> g_G
//   GEMM3: St[n][p] = sum_l Bw[l][n]*Xs[l][p]                          -> g_states
//   (ecl=exp(cs) folded into Cte; em=exp(A-cs); w=exp(tot-cs) folded into Bw)
// ---------------------------------------------------------------------------
__global__ void __launch_bounds__(128, 3) pass1_kernel(
    const float* __restrict__ X, const float* __restrict__ A,
    const float* __restrict__ B, const float* __restrict__ C)
{
    extern __shared__ float sm[];
    float* Xs  = sm;                                   // [64][PADS] X straight
    float* Bw  = sm + 64*PADS;                         // [64][PADS] B*w straight
    float* Bt  = sm + 2*64*PADS;                       // [64][PADT] B^T
    float* Cte = sm + 2*64*PADS + 64*PADT;             // [64][PADT] C^T*ecl
    __shared__ float s_cs[64], s_w[64], s_em[64], s_ecl[64];

    const int c = blockIdx.x, h = blockIdx.y, b = blockIdx.z;
    const int bhc = (b*NH + h)*NC + c;
    const int tid = threadIdx.x;
    const int tx = tid & 15, ty = tid >> 4;
    const size_t base = ((size_t)((b*4096 + c*64)*NH + h))*64;
    const int col4 = tx*4;

    // cumsum of A first (threads 0..63)
    if (tid < 64) {
        const float av = A[(size_t)(b*4096 + c*64 + tid)*NH + h];
        float v = av;
        #pragma unroll
        for (int o = 1; o < 32; o <<= 1) {
            float t = __shfl_up_sync(0xffffffffu, v, o);
            if ((tid & 31) >= o) v += t;
        }
        s_cs[tid] = v;
        s_em[tid] = av;       // stash A
    }
    __syncthreads();
    if (tid >= 32 && tid < 64) s_cs[tid] += s_cs[31];
    __syncthreads();
    if (tid < 64) {
        const float csl = s_cs[tid], total = s_cs[63];
        s_ecl[tid] = __expf(csl);
        s_em[tid]  = __expf(s_em[tid] - csl);
        s_w[tid]   = __expf(total - csl);
        if (tid == 63) g_tot[bhc] = total;
    }
    __syncthreads();

    // tile loads: X straight; B -> Bw (scaled) + Bt (transposed); C -> Cte
    #pragma unroll
    for (int i = 0; i < 8; i++) {
        const int row = i*8 + ty;
        const size_t g = base + (size_t)row*1024 + col4;
        *(float4*)(Xs + row*PADS + col4) = *(const float4*)(X + g);
        float4 bf = *(const float4*)(B + g);
        float4 cf = *(const float4*)(C + g);
        const float w = s_w[row], e = s_ecl[row];
        float4 bw = make_float4(bf.x*w, bf.y*w, bf.z*w, bf.w*w);
        *(float4*)(Bw + row*PADS + col4) = bw;
        float cs[4] = {cf.x*e, cf.y*e, cf.z*e, cf.w*e};
        const float* bp = (const float*)&bf;
        #pragma unroll
        for (int q = 0; q < 4; q++) {
            const int eq = (q + (tx >> 1)) & 3;   // rotation: <=2-way conflicts
            Bt [(col4 + eq)*PADT + row] = bp[eq];
            Cte[(col4 + eq)*PADT + row] = cs[eq];
        }
    }
    __syncthreads();

    const int rb = ty*8, cb = col4;

    // ---- GEMM1: rows s (pairs), cols l; k=n ----
    {
        ull acc[4][4] = {};
        #pragma unroll 4
        for (int k = 0; k < 64; k++) {
            F4U a0, a1, bf;
            a0.f = *(const float4*)(Bt + k*PADT + rb);
            a1.f = *(const float4*)(Bt + k*PADT + rb + 4);
            bf.f = *(const float4*)(Cte + k*PADT + cb);
            const ull b0 = pack2(bf.f.x, bf.f.x), b1 = pack2(bf.f.y, bf.f.y);
            const ull b2 = pack2(bf.f.z, bf.f.z), b3 = pack2(bf.f.w, bf.f.w);
            const ull ap[4] = {a0.u[0], a0.u[1], a1.u[0], a1.u[1]};
            #pragma unroll
            for (int ii = 0; ii < 4; ii++) {
                acc[ii][0] = ffma2(ap[ii], b0, acc[ii][0]);
                acc[ii][1] = ffma2(ap[ii], b1, acc[ii][1]);
                acc[ii][2] = ffma2(ap[ii], b2, acc[ii][2]);
                acc[ii][3] = ffma2(ap[ii], b3, acc[ii][3]);
            }
        }
        float* gt = g_G + (size_t)bhc*4096;
        #pragma unroll
        for (int ii = 0; ii < 4; ii++) {
            const int s0 = rb + 2*ii, s1 = s0 + 1;
            const float em0 = s_em[s0], em1 = s_em[s1];
            float r0[4], r1[4];
            #pragma unroll
            for (int j = 0; j < 4; j++) {
                const float2 v = unpk(acc[ii][j]);
                const int l = cb + j;
                r0[j] = (l >= s0) ? v.x * em0 : 0.f;
                r1[j] = (l >= s1) ? v.y * em1 : 0.f;
            }
            *(float4*)(gt + s0*64 + cb) = make_float4(r0[0], r0[1], r0[2], r0[3]);
            *(float4*)(gt + s1*64 + cb) = make_float4(r1[0], r1[1], r1[2], r1[3]);
        }
    }

    // ---- GEMM3: rows n (pairs), cols p; k=l ----
    {
        ull acc[4][4] = {};
        #pragma unroll 4
        for (int k = 0; k < 64; k++) {
            F4U a0, a1, xf;
            a0.f = *(const float4*)(Bw + k*PADS + rb);
            a1.f = *(const float4*)(Bw + k*PADS + rb + 4);
            xf.f = *(const float4*)(Xs + k*PADS + cb);
            const ull b0 = pack2(xf.f.x, xf.f.x), b1 = pack2(xf.f.y, xf.f.y);
            const ull b2 = pack2(xf.f.z, xf.f.z), b3 = pack2(xf.f.w, xf.f.w);
            const ull ap[4] = {a0.u[0], a0.u[1], a1.u[0], a1.u[1]};
            #pragma unroll
            for (int ii = 0; ii < 4; ii++) {
                acc[ii][0] = ffma2(ap[ii], b0, acc[ii][0]);
                acc[ii][1] = ffma2(ap[ii], b1, acc[ii][1]);
                acc[ii][2] = ffma2(ap[ii], b2, acc[ii][2]);
                acc[ii][3] = ffma2(ap[ii], b3, acc[ii][3]);
            }
        }
        float* st = g_states + (size_t)bhc*4096;
        #pragma unroll
        for (int ii = 0; ii < 4; ii++) {
            const int n0 = rb + 2*ii, n1 = n0 + 1;
            const float2 v0 = unpk(acc[ii][0]), v1 = unpk(acc[ii][1]);
            const float2 v2 = unpk(acc[ii][2]), v3 = unpk(acc[ii][3]);
            *(float4*)(st + n0*64 + cb) = make_float4(v0.x, v1.x, v2.x, v3.x);
            *(float4*)(st + n1*64 + cb) = make_float4(v0.y, v1.y, v2.y, v3.y);
        }
    }
}

// ---------------------------------------------------------------------------
// Pass 2: inter-chunk scan, in place. S_out[c] = S_before; S = e_c*(S + v_c).
// ---------------------------------------------------------------------------
__global__ void __launch_bounds__(128) pass2_kernel()
{
    __shared__ float se[NC];
    const int slice = blockIdx.x, bh = blockIdx.y;
    const int tid = threadIdx.x;

    if (tid < NC) se[tid] = __expf(g_tot[bh*NC + tid]);
    __syncthreads();

    float* p = g_states + (size_t)bh*NC*4096 + slice*512 + tid*4;
    float4 v[8];
    #pragma unroll
    for (int j = 0; j < 8; j++) v[j] = *(float4*)(p + (size_t)j*4096);

    float4 S = make_float4(0.f, 0.f, 0.f, 0.f);
    #pragma unroll 8
    for (int c = 0; c < NC; c++) {
        float4 cur = v[c & 7];
        *(float4*)(p + (size_t)c*4096) = S;           // state BEFORE chunk c
        const float e = se[c];
        S.x = e * (S.x + cur.x);
        S.y = e * (S.y + cur.y);
        S.z = e * (S.z + cur.z);
        S.w = e * (S.w + cur.w);
        if (c + 8 < NC) v[c & 7] = *(float4*)(p + (size_t)(c+8)*4096);
    }
}

// ---------------------------------------------------------------------------
// Pass 3: single fused k-loop, transposed acc:
//   Y[l][p] = sum_k Gt[k][l]*X[k][p] + sum_k Cte[k][l]*St[k][p]
// Gt streamed from g_G (L2-hot) with branchless reg double-buffer.
// 128 threads, 8x4 micro-tiles, 4 CTAs/SM (50 KB smem).
// ---------------------------------------------------------------------------
__global__ void __launch_bounds__(128, 4) pass3_kernel(
    const float* __restrict__ X, const float* __restrict__ A,
    const float* __restrict__ C, float* __restrict__ Y)
{
    extern __shared__ float sm[];
    float* Xs  = sm;                          // [64][PADS]
    float* Ss  = sm + 64*PADS;                // [64][PADS]
    float* Cte = sm + 2*64*PADS;              // [64][PADT] C^T * ecl
    __shared__ float s_cs[64], s_ecl[64];

    const int c = blockIdx.x, h = blockIdx.y, b = blockIdx.z;
    const int bhc = (b*NH + h)*NC + c;
    const int tid = threadIdx.x;
    const int tx = tid & 15, ty = tid >> 4;
    const size_t base = ((size_t)((b*4096 + c*64)*NH + h))*64;
    const float* Sg = g_states + (size_t)bhc*4096;
    const int col4 = tx*4;

    // cumsum -> ecl
    if (tid < 64) {
        float v = A[(size_t)(b*4096 + c*64 + tid)*NH + h];
        #pragma unroll
        for (int o = 1; o < 32; o <<= 1) {
            float t = __shfl_up_sync(0xffffffffu, v, o);
            if ((tid & 31) >= o) v += t;
        }
        s_cs[tid] = v;
    }
    __syncthreads();
    if (tid >= 32 && tid < 64) s_cs[tid] += s_cs[31];
    __syncthreads();
    if (tid < 64) s_ecl[tid] = __expf(s_cs[tid]);
    __syncthreads();

    // loads: X, S straight; C -> Cte transposed scaled
    #pragma unroll
    for (int i = 0; i < 8; i++) {
        const int row = i*8 + ty;
        *(float4*)(Xs + row*PADS + col4) =
            *(const float4*)(X + base + (size_t)row*1024 + col4);
        *(float4*)(Ss + row*PADS + col4) = *(const float4*)(Sg + row*64 + col4);
        float4 cf = *(const float4*)(C + base + (size_t)row*1024 + col4);
        const float e = s_ecl[row];
        float cs[4] = {cf.x*e, cf.y*e, cf.z*e, cf.w*e};
        #pragma unroll
        for (int q = 0; q < 4; q++) {
            const int eq = (q + (tx >> 1)) & 3;
            Cte[(col4 + eq)*PADT + row] = cs[eq];
        }
    }
    __syncthreads();

    const int rb = ty*8, cb = col4;

    // fused GEMM2+GEMM4
    ull acc[4][4] = {};
    const float* gt = g_G + (size_t)bhc*4096;
    F4U ga0, ga1;
    ga0.f = __ldg((const float4*)(gt + rb));
    ga1.f = __ldg((const float4*)(gt + rb + 4));
    #pragma unroll 4
    for (int k = 0; k < 64; k++) {
        const int kn = (k + 1) & 63;                 // branchless wrap prefetch
        F4U na0, na1, ca0, ca1, xf, sf;
        na0.f = __ldg((const float4*)(gt + kn*64 + rb));
        na1.f = __ldg((const float4*)(gt + kn*64 + rb + 4));
        ca0.f = *(const float4*)(Cte + k*PADT + rb);
        ca1.f = *(const float4*)(Cte + k*PADT + rb + 4);
        xf.f  = *(const float4*)(Xs + k*PADS + cb);
        sf.f  = *(const float4*)(Ss + k*PADS + cb);
        const ull x0 = pack2(xf.f.x, xf.f.x), x1 = pack2(xf.f.y, xf.f.y);
        const ull x2 = pack2(xf.f.z, xf.f.z), x3 = pack2(xf.f.w, xf.f.w);
        const ull s0 = pack2(sf.f.x, sf.f.x), s1 = pack2(sf.f.y, sf.f.y);
        const ull s2 = pack2(sf.f.z, sf.f.z), s3 = pack2(sf.f.w, sf.f.w);
        const ull gp[4] = {ga0.u[0], ga0.u[1], ga1.u[0], ga1.u[1]};
        const ull cp[4] = {ca0.u[0], ca0.u[1], ca1.u[0], ca1.u[1]};
        #pragma unroll
        for (int ii = 0; ii < 4; ii++) {
            acc[ii][0] = ffma2(gp[ii], x0, acc[ii][0]);
            acc[ii][1] = ffma2(gp[ii], x1, acc[ii][1]);
            acc[ii][2] = ffma2(gp[ii], x2, acc[ii][2]);
            acc[ii][3] = ffma2(gp[ii], x3, acc[ii][3]);
        }
        #pragma unroll
        for (int ii = 0; ii < 4; ii++) {
            acc[ii][0] = ffma2(cp[ii], s0, acc[ii][0]);
            acc[ii][1] = ffma2(cp[ii], s1, acc[ii][1]);
            acc[ii][2] = ffma2(cp[ii], s2, acc[ii][2]);
            acc[ii][3] = ffma2(cp[ii], s3, acc[ii][3]);
        }
        ga0 = na0; ga1 = na1;
    }

    #pragma unroll
    for (int ii = 0; ii < 4; ii++) {
        const int l0 = rb + 2*ii, l1 = l0 + 1;
        const float2 v0 = unpk(acc[ii][0]), v1 = unpk(acc[ii][1]);
        const float2 v2 = unpk(acc[ii][2]), v3 = unpk(acc[ii][3]);
        *(float4*)(Y + base + (size_t)l0*1024 + cb) =
            make_float4(v0.x, v1.x, v2.x, v3.x);
        *(float4*)(Y + base + (size_t)l1*1024 + cb) =
            make_float4(v0.y, v1.y, v2.y, v3.y);
    }
}

// ---------------------------------------------------------------------------
extern "C" void kernel_launch(void* const* d_in, const int* in_sizes, int n_in,
                              void* d_out, int out_size)
{
    const float* X = (const float*)d_in[0];
    const float* A = (const float*)d_in[1];
    const float* B = (const float*)d_in[2];
    const float* C = (const float*)d_in[3];
    float* Y = (float*)d_out;

    const int smem1 = (2*64*PADS + 2*64*PADT) * sizeof(float);  // 67,584 B
    const int smem3 = (2*64*PADS + 64*PADT) * sizeof(float);    // 50,176 B
    cudaFuncSetAttribute(pass1_kernel,
                         cudaFuncAttributeMaxDynamicSharedMemorySize, smem1);
    cudaFuncSetAttribute(pass3_kernel,
                         cudaFuncAttributeMaxDynamicSharedMemorySize, smem3);

    dim3 grid(NC, NH, NB);
    pass1_kernel<<<grid, 128, smem1>>>(X, A, B, C);
    pass2_kernel<<<dim3(8, NB*NH), 128>>>();
    pass3_kernel<<<grid, 128, smem3>>>(X, A, C, Y);
}